// round 14
// baseline (speedup 1.0000x reference)
#include <cuda_runtime.h>
#include <cuda_bf16.h>
#include <cstdint>
#include <cstring>

#define Bsz 256
#define Tt  200
#define Dd  128
#define Oo  128
#define RPB 2
#define NBLK (Bsz/RPB)     // 128 scan CTAs
#define NTHR 256
#define SCTH 1024          // scan threads: 8 k-groups x 128 h-threads
#define SGRP 8
#define KPAD 272           // 256 k's + 16 zero pad for prefetch overrun
#define K2PAD 136          // padded k-pairs
#define BT  (Bsz*Tt)       // 51200
#define RPP 8              // bt-rows per G-precompute CTA
#define EROWS 32           // bt-rows per epilogue CTA

typedef unsigned long long u64;

// ---------------- device globals (no allocs allowed) ----------------
// A weights, k-pair layout: ulonglong2[(k2*256+h)*2 + half]
//   half0 = { (Ai[k0],Ai[k1]), (Af[k0],Af[k1]) },  half1 = { (Ao..), (Ac..) }   (f32 pairs)
__device__ __align__(16) ulonglong2 g_Ap[K2PAD * 256 * 2];
// bf16 gate weights: [k][hid] uint4 = { if(h0), oc(h0), if(h1), oc(h1) }; h0=hid, h1=hid+128
__device__ __align__(16) unsigned int g_Bhh[KPAD * 128 * 4];
__device__ __align__(16) float4 g_bias4[256];        // folded gate biases
__device__ float  g_WmT[4 * 64 * 256];               // transposed W*[:,0:64]: [g][m][h]
__device__ float  g_Wqh[64 * 256];                   // Wq_h = Wq[:,256:384] @ Wfc   [m][hc]
__device__ float  g_bqe[64];                         // bq + Wq[:,256:] @ bfc
__device__ __align__(8) float2 g_WfcT2[128 * 128];   // [hp][o] = (Wfc[o][2hp], Wfc[o][2hp+1])
__device__ float  g_wzd[128], g_wzpd[128];
__device__ __align__(16) float4 g_G4[(long)BT * 256];// 200 MB: precomputed A@[z,zp]+bias
__device__ float  g_H [(long)BT * 256];              // 50 MB: h_t for the epilogue

// ---------------- helpers ----------------
__device__ __forceinline__ float fast_sigmoid(float x) { return 1.0f / (1.0f + __expf(-x)); }
__device__ __forceinline__ float fast_tanh(float x)    { return 1.0f - 2.0f / (__expf(2.0f * x) + 1.0f); }
__device__ __forceinline__ u64 pack2(float lo, float hi) {
    u64 r; asm("mov.b64 %0, {%1, %2};" : "=l"(r) : "f"(lo), "f"(hi)); return r;
}
__device__ __forceinline__ u64 dup2(float v) {
    u64 r; asm("mov.b64 %0, {%1, %1};" : "=l"(r) : "f"(v)); return r;
}
__device__ __forceinline__ void unpack2(u64 v, float& lo, float& hi) {
    asm("mov.b64 {%0, %1}, %2;" : "=f"(lo), "=f"(hi) : "l"(v));
}
__device__ __forceinline__ void fma2(u64& d, u64 a, u64 b) {
    asm("fma.rn.f32x2 %0, %1, %2, %0;" : "+l"(d) : "l"(a), "l"(b));
}
__device__ __forceinline__ u64 add2(u64 a, u64 b) {
    u64 r; asm("add.rn.f32x2 %0, %1, %2;" : "=l"(r) : "l"(a), "l"(b)); return r;
}
__device__ __forceinline__ ulonglong2 ldcg_v2(const ulonglong2* p) {
    ulonglong2 v;
    asm("ld.global.cg.v2.b64 {%0, %1}, [%2];" : "=l"(v.x), "=l"(v.y) : "l"(p));
    return v;
}
// bf16x2 (packed in 32-bit) -> f32x2 in a 64-bit lane: fp32 = bf16 << 16 (exact)
__device__ __forceinline__ u64 bf2f2(unsigned int w) {
    unsigned int lo = w << 16;
    unsigned int hi = w & 0xffff0000u;
    u64 r; asm("mov.b64 %0, {%1, %2};" : "=l"(r) : "r"(lo), "r"(hi)); return r;
}
__device__ __forceinline__ unsigned short f2bf(float x) {
    __nv_bfloat16 b = __float2bfloat16(x);
    unsigned short s; memcpy(&s, &b, 2); return s;
}

// ================= prep0: transpose W*[:,0:64] for coalesced prep2 =================
__global__ void prep0_kernel(const float* __restrict__ Wi, const float* __restrict__ Wf,
                             const float* __restrict__ Wo, const float* __restrict__ Wc)
{
    int m = blockIdx.x, h = threadIdx.x;      // grid 64, block 256
    g_WmT[(0 * 64 + m) * 256 + h] = Wi[h * 320 + m];
    g_WmT[(1 * 64 + m) * 256 + h] = Wf[h * 320 + m];
    g_WmT[(2 * 64 + m) * 256 + h] = Wo[h * 320 + m];
    g_WmT[(3 * 64 + m) * 256 + h] = Wc[h * 320 + m];
}

// ================= prep1: Wq_h = Wq_xi @ Wfc ; bq_eff =================
__global__ void prep1_kernel(const float* __restrict__ Wq, const float* __restrict__ Wfc,
                             const float* __restrict__ bq, const float* __restrict__ bfc)
{
    int m = blockIdx.x, hc = threadIdx.x;     // grid 64, block 256
    float s = 0.0f;
    for (int o = 0; o < 128; o++)
        s = fmaf(Wq[m * 384 + 256 + o], Wfc[o * 256 + hc], s);
    g_Wqh[m * 256 + hc] = s;
    if (hc == 0) {
        float s2 = bq[m];
        for (int o = 0; o < 128; o++)
            s2 = fmaf(Wq[m * 384 + 256 + o], bfc[o], s2);
        g_bqe[m] = s2;
    }
}

// ================= prep2: fold A (k-pair layout), Bh (bf16), biases; misc ============
__global__ void prep2_kernel(const float* __restrict__ Wz, const float* __restrict__ Wzp,
                             const float* __restrict__ Wq,
                             const float* __restrict__ Wi, const float* __restrict__ bi,
                             const float* __restrict__ Wf, const float* __restrict__ bf,
                             const float* __restrict__ Wo, const float* __restrict__ bo,
                             const float* __restrict__ Wc, const float* __restrict__ bc,
                             const float* __restrict__ Wfc)
{
    int k = blockIdx.x, h = threadIdx.x;      // grid KPAD(272), block 256
    float4 bh = make_float4(0.f, 0.f, 0.f, 0.f);
    float4 a  = make_float4(0.f, 0.f, 0.f, 0.f);
    if (k < 256) {
        bh.x = Wi[h * 320 + 64 + k];
        bh.y = Wf[h * 320 + 64 + k];
        bh.z = Wo[h * 320 + 64 + k];
        bh.w = Wc[h * 320 + 64 + k];
        for (int m = 0; m < 64; m++) {
            float q  = Wq[m * 384 + k];          // uniform across CTA
            float qh = g_Wqh[m * 256 + k];       // uniform across CTA
            float wi = g_WmT[(0 * 64 + m) * 256 + h];   // coalesced
            float wf = g_WmT[(1 * 64 + m) * 256 + h];
            float wo = g_WmT[(2 * 64 + m) * 256 + h];
            float wc = g_WmT[(3 * 64 + m) * 256 + h];
            a.x = fmaf(wi, q, a.x);  a.y = fmaf(wf, q, a.y);
            a.z = fmaf(wo, q, a.z);  a.w = fmaf(wc, q, a.w);
            bh.x = fmaf(wi, qh, bh.x); bh.y = fmaf(wf, qh, bh.y);
            bh.z = fmaf(wo, qh, bh.z); bh.w = fmaf(wc, qh, bh.w);
        }
    }
    // A k-pair layout: float offset = ((k2*256+h)*2 + g>>1)*4 + (g&1)*2 + parity
    {
        int k2 = k >> 1, p = k & 1;
        float* apf = reinterpret_cast<float*>(g_Ap);
        long base = ((long)(k2 * 256 + h) * 2) * 4;
        apf[base + 0 + p] = a.x;   // gate i (half0 lane0)
        apf[base + 2 + p] = a.y;   // gate f (half0 lane1)
        apf[base + 4 + p] = a.z;   // gate o (half1 lane0)
        apf[base + 6 + p] = a.w;   // gate c (half1 lane1)
    }
    // bf16 Bh pack: unit [k][h&127], halves by h>>7
    {
        unsigned int u_if = (unsigned int)f2bf(bh.x) | ((unsigned int)f2bf(bh.y) << 16);
        unsigned int u_oc = (unsigned int)f2bf(bh.z) | ((unsigned int)f2bf(bh.w) << 16);
        unsigned int* dst = g_Bhh + (k * 128 + (h & 127)) * 4 + ((h >> 7) << 1);
        dst[0] = u_if;
        dst[1] = u_oc;
    }
    if (k == 0) {
        float4 b4 = make_float4(bi[h], bf[h], bo[h], bc[h]);
        for (int m = 0; m < 64; m++) {
            float e = g_bqe[m];
            b4.x = fmaf(g_WmT[(0 * 64 + m) * 256 + h], e, b4.x);
            b4.y = fmaf(g_WmT[(1 * 64 + m) * 256 + h], e, b4.y);
            b4.z = fmaf(g_WmT[(2 * 64 + m) * 256 + h], e, b4.z);
            b4.w = fmaf(g_WmT[(3 * 64 + m) * 256 + h], e, b4.w);
        }
        g_bias4[h] = b4;
    }
    if (k == 1 && h < 128) {
        g_wzd[h]  = Wz[h * 128 + h];
        g_wzpd[h] = Wzp[h * 128 + h];
    }
    if (k < 128 && h < 128)
        g_WfcT2[k * 128 + h] = make_float2(Wfc[h * 256 + 2 * k], Wfc[h * 256 + 2 * k + 1]);
}

// ================= G precompute: G = A @ [z,zp] + bias (k-pair lanes) =================
__global__ __launch_bounds__(NTHR, 2) void gpre_kernel(
    const float* __restrict__ inp, const float* __restrict__ xmean,
    const float* __restrict__ bz,  const float* __restrict__ bzp)
{
    __shared__ __align__(16) float su[RPP * 256];    // 8 KB, NOT duplicated
    __shared__ float s_wzd[128], s_bz[128], s_wzpd[128], s_bzp[128];

    const int tid = threadIdx.x;
    const int bt0 = blockIdx.x * RPP;                 // grid = BT/RPP = 6400

    if (tid < 128) {
        s_wzd[tid] = g_wzd[tid];   s_bz[tid]  = bz[tid];
        s_wzpd[tid] = g_wzpd[tid]; s_bzp[tid] = bzp[tid];
    }
    __syncthreads();

    const long cs = (long)Tt * Dd;
    for (int e = tid; e < RPP * 128; e += NTHR) {
        int row = e >> 7, j = e & 127;
        int bt = bt0 + row, b = bt / Tt, t = bt - b * Tt;
        long base = ((long)b * 6 * Tt + t) * (long)Dd + j;
        float x   = inp[base];
        float xl  = inp[base + 1 * cs];
        float mk  = inp[base + 2 * cs];
        float dl  = inp[base + 3 * cs];
        float xlb = inp[base + 4 * cs];
        float dlb = inp[base + 5 * cs];
        float xm  = xmean[((long)b * Tt + t) * (long)Dd + j];
        float dz  = __expf(-fmaxf(fmaf(dl,  s_wzd[j],  s_bz[j]),  0.0f));
        float dzp = __expf(-fmaxf(fmaf(dlb, s_wzpd[j], s_bzp[j]), 0.0f));
        su[row * 256 + j]       = mk * x + (1.0f - mk) * (dz  * xl  + (1.0f - dz)  * xm);
        su[row * 256 + 128 + j] = mk * x + (1.0f - mk) * (dzp * xlb + (1.0f - dzp) * xm);
    }
    __syncthreads();

    // accumulators per row per gate; lanes = (even k, odd k) partials
    u64 aI[RPP], aF[RPP], aO[RPP], aC[RPP];
#pragma unroll
    for (int r = 0; r < RPP; r++) { aI[r] = 0ull; aF[r] = 0ull; aO[r] = 0ull; aC[r] = 0ull; }

    const ulonglong2* __restrict__ wg = g_Ap + tid * 2;   // (k2*256+h)*2 indexing
    const float4* su4 = reinterpret_cast<const float4*>(su);

    // double-buffer one kq (= 2 k-pairs = 4 k) ahead
    ulonglong2 wA0 = ldcg_v2(wg + 0);
    ulonglong2 wA1 = ldcg_v2(wg + 1);
    ulonglong2 wB0 = ldcg_v2(wg + 512);
    ulonglong2 wB1 = ldcg_v2(wg + 513);
#pragma unroll 1
    for (int kq = 0; kq < 64; kq++) {
        ulonglong2 a0 = wA0, a1 = wA1, b0w = wB0, b1w = wB1;
        const ulonglong2* nxt = wg + (2 * kq + 2) * 512;  // k2 = 2kq+2 (pad covers overrun)
        wA0 = ldcg_v2(nxt);
        wA1 = ldcg_v2(nxt + 1);
        wB0 = ldcg_v2(nxt + 512);
        wB1 = ldcg_v2(nxt + 513);
#pragma unroll
        for (int r = 0; r < RPP; r++) {
            float4 uu = su4[r * 64 + kq];
            u64 p0 = pack2(uu.x, uu.y);    // k-pair 2kq
            u64 p1 = pack2(uu.z, uu.w);    // k-pair 2kq+1
            fma2(aI[r], a0.x, p0);  fma2(aF[r], a0.y, p0);
            fma2(aO[r], a1.x, p0);  fma2(aC[r], a1.y, p0);
            fma2(aI[r], b0w.x, p1); fma2(aF[r], b0w.y, p1);
            fma2(aO[r], b1w.x, p1); fma2(aC[r], b1w.y, p1);
        }
    }

    const float4 b4 = g_bias4[tid];
#pragma unroll
    for (int r = 0; r < RPP; r++) {
        float lo, hi, gi, gf, go, gc;
        unpack2(aI[r], lo, hi); gi = b4.x + lo + hi;
        unpack2(aF[r], lo, hi); gf = b4.y + lo + hi;
        unpack2(aO[r], lo, hi); go = b4.z + lo + hi;
        unpack2(aC[r], lo, hi); gc = b4.w + lo + hi;
        g_G4[(long)(bt0 + r) * 256 + tid] = make_float4(gi, gf, go, gc);
    }
}

// ================= scan: 128 CTAs (2 rows), 1024 threads = 8 k-groups x 128 h ==========
__global__ __launch_bounds__(SCTH, 1) void scan_kernel()
{
    extern __shared__ __align__(16) char smraw[];
    u64* hdup = reinterpret_cast<u64*>(smraw);                    // [2][RPB][256]     8192 B
    u64* part = reinterpret_cast<u64*>(smraw + 2 * RPB * 256 * 8);// [8][RPB][256][2] 65536 B

    const int tid = threadIdx.x;
    const int g   = tid >> 7;          // k-group 0..7
    const int hid = tid & 127;
    const int h0  = hid, h1 = hid + 128;
    const int b0  = blockIdx.x * RPB;
    const int kb  = g << 5;            // group k-base: 0,32,...,224

    for (int i = tid; i < 2 * RPB * 256; i += SCTH) hdup[i] = 0ull;        // h0 = 0

    float c_reg = 0.0f;                // threads tid<512 own 1 output (row tid>>8, h tid&255)
    __syncthreads();

    const uint4* __restrict__ wb16 = reinterpret_cast<const uint4*>(g_Bhh) + hid;  // [k][hid]
    const float4* __restrict__ G4 = g_G4;

    for (int t = 0; t < Tt; t++) {
        const int cur = t & 1, prv = cur ^ 1;
        const u64* hp = hdup + prv * (RPB * 256);

        // groups 1,2 issue G loads now; consumed at deposit (GEMM hides latency)
        float4 gvl[RPB];
        if (g == 1) {
#pragma unroll
            for (int r = 0; r < RPB; r++) gvl[r] = G4[((long)(b0 + r) * Tt + t) * 256 + h0];
        } else if (g == 2) {
#pragma unroll
            for (int r = 0; r < RPB; r++) gvl[r] = G4[((long)(b0 + r) * Tt + t) * 256 + h1];
        }

        u64 aif0[RPB], aoc0[RPB], aif1[RPB], aoc1[RPB];
#pragma unroll
        for (int r = 0; r < RPB; r++) { aif0[r] = 0ull; aoc0[r] = 0ull; aif1[r] = 0ull; aoc1[r] = 0ull; }

        // prefetch 2 k's (bf16, one uint4 per k covers both h's)
        uint4 wq0 = __ldcg(wb16 + (kb + 0) * 128);
        uint4 wq1 = __ldcg(wb16 + (kb + 1) * 128);

        // ---- 32 k streamed (bf16), 16 iterations of 2 k ----
#pragma unroll 1
        for (int k0 = kb; k0 < kb + 32; k0 += 2) {
            uint4 a0 = wq0, a1 = wq1;
            wq0 = __ldcg(wb16 + (k0 + 2) * 128);   // KPAD pad covers overrun
            wq1 = __ldcg(wb16 + (k0 + 3) * 128);
            u64 wa_if0 = bf2f2(a0.x), wa_oc0 = bf2f2(a0.y), wa_if1 = bf2f2(a0.z), wa_oc1 = bf2f2(a0.w);
            u64 wc_if0 = bf2f2(a1.x), wc_oc0 = bf2f2(a1.y), wc_if1 = bf2f2(a1.z), wc_oc1 = bf2f2(a1.w);
#pragma unroll
            for (int r = 0; r < RPB; r++) {
                ulonglong2 hh = *reinterpret_cast<const ulonglong2*>(&hp[r * 256 + k0]);
                fma2(aif0[r], wa_if0, hh.x); fma2(aoc0[r], wa_oc0, hh.x);
                fma2(aif1[r], wa_if1, hh.x); fma2(aoc1[r], wa_oc1, hh.x);
                fma2(aif0[r], wc_if0, hh.y); fma2(aoc0[r], wc_oc0, hh.y);
                fma2(aif1[r], wc_if1, hh.y); fma2(aoc1[r], wc_oc1, hh.y);
            }
        }

        // ---- fold G, deposit partials ----
        if (g == 1) {
#pragma unroll
            for (int r = 0; r < RPB; r++) {
                aif0[r] = add2(aif0[r], pack2(gvl[r].x, gvl[r].y));
                aoc0[r] = add2(aoc0[r], pack2(gvl[r].z, gvl[r].w));
            }
        } else if (g == 2) {
#pragma unroll
            for (int r = 0; r < RPB; r++) {
                aif1[r] = add2(aif1[r], pack2(gvl[r].x, gvl[r].y));
                aoc1[r] = add2(aoc1[r], pack2(gvl[r].z, gvl[r].w));
            }
        }
#pragma unroll
        for (int r = 0; r < RPB; r++) {
            ulonglong2 p0; p0.x = aif0[r]; p0.y = aoc0[r];
            ulonglong2 p1; p1.x = aif1[r]; p1.y = aoc1[r];
            *reinterpret_cast<ulonglong2*>(&part[((g * RPB + r) * 256 + h0) * 2]) = p0;
            *reinterpret_cast<ulonglong2*>(&part[((g * RPB + r) * 256 + h1) * 2]) = p1;
        }
        __syncthreads();

        // ---- threads <512: 8-way reduce, activations, publish (1 output/thread) ----
        if (tid < 512) {
            const int hh_ = tid & 255;
            const int rr  = tid >> 8;           // 0 or 1
            u64 tif = 0ull, toc = 0ull;
#pragma unroll
            for (int q = 0; q < SGRP; q++) {
                ulonglong2 p = *reinterpret_cast<const ulonglong2*>(&part[((q * RPB + rr) * 256 + hh_) * 2]);
                tif = add2(tif, p.x);
                toc = add2(toc, p.y);
            }
            float ai, afv, ao, ac;
            unpack2(tif, ai, afv); unpack2(toc, ao, ac);
            float ig = fast_sigmoid(ai), fg = fast_sigmoid(afv);
            float og = fast_sigmoid(ao), ct = fast_tanh(ac);
            c_reg = fg * c_reg + ig * ct;
            float hv = og * fast_tanh(c_reg);
            hdup[cur * (RPB * 256) + rr * 256 + hh_] = dup2(hv);
            g_H[((long)(b0 + rr) * Tt + t) * 256 + hh_] = hv;
        }
        __syncthreads();
    }
}

// ================= epilogue: out = H @ Wfc^T + bfc (fully parallel) =================
__global__ __launch_bounds__(NTHR) void epi_kernel(const float* __restrict__ bfc,
                                                   float* __restrict__ out)
{
    __shared__ __align__(16) float hs[EROWS * 256];   // 32 KB
    const int tid = threadIdx.x;
    const int bt0 = blockIdx.x * EROWS;               // grid = BT/EROWS = 1600

    for (int e = tid; e < EROWS * 256; e += NTHR)
        hs[e] = g_H[(long)bt0 * 256 + e];
    __syncthreads();

    const int o  = tid & 127;
    const int rb = (tid >> 7) * 16;                   // rows rb .. rb+15
    u64 acc[16];
#pragma unroll
    for (int r = 0; r < 16; r++) acc[r] = 0ull;

    const u64* __restrict__ w2 = reinterpret_cast<const u64*>(g_WfcT2) + o;
#pragma unroll 4
    for (int hpi = 0; hpi < 128; hpi++) {
        u64 w = w2[hpi * 128];
#pragma unroll
        for (int r = 0; r < 16; r++)
            fma2(acc[r], w, *reinterpret_cast<const u64*>(&hs[(rb + r) * 256 + 2 * hpi]));
    }
    const float bo_ = bfc[o];
#pragma unroll
    for (int r = 0; r < 16; r++) {
        float x0, x1; unpack2(acc[r], x0, x1);
        out[(long)(bt0 + rb + r) * Oo + o] = bo_ + x0 + x1;
    }
}

// ================= launch =================
#define SCAN_SMEM (2*RPB*256*8 + SGRP*RPB*256*2*8)   // 8192 + 65536 = 73728

extern "C" void kernel_launch(void* const* d_in, const int* in_sizes, int n_in,
                              void* d_out, int out_size)
{
    const float* inp   = (const float*)d_in[0];
    const float* xmean = (const float*)d_in[1];
    const float* Wz    = (const float*)d_in[2];
    const float* bz    = (const float*)d_in[3];
    const float* Wzp   = (const float*)d_in[4];
    const float* bzp   = (const float*)d_in[5];
    const float* Wq    = (const float*)d_in[6];
    const float* bq    = (const float*)d_in[7];
    const float* Wi    = (const float*)d_in[8];
    const float* bi    = (const float*)d_in[9];
    const float* Wf    = (const float*)d_in[10];
    const float* bf    = (const float*)d_in[11];
    const float* Wo    = (const float*)d_in[12];
    const float* bo    = (const float*)d_in[13];
    const float* Wc    = (const float*)d_in[14];
    const float* bc    = (const float*)d_in[15];
    const float* Wfc   = (const float*)d_in[16];
    const float* bfc   = (const float*)d_in[17];
    float* out = (float*)d_out;

    cudaFuncSetAttribute(scan_kernel, cudaFuncAttributeMaxDynamicSharedMemorySize, SCAN_SMEM);

    prep0_kernel<<<64, 256>>>(Wi, Wf, Wo, Wc);
    prep1_kernel<<<64, 256>>>(Wq, Wfc, bq, bfc);
    prep2_kernel<<<KPAD, 256>>>(Wz, Wzp, Wq, Wi, bi, Wf, bf, Wo, bo, Wc, bc, Wfc);
    gpre_kernel<<<BT / RPP, NTHR>>>(inp, xmean, bz, bzp);
    scan_kernel<<<NBLK, SCTH, SCAN_SMEM>>>();
    epi_kernel<<<BT / EROWS, NTHR>>>(bfc, out);
}

// round 15
// speedup vs baseline: 1.2119x; 1.2119x over previous
#include <cuda_runtime.h>
#include <cuda_bf16.h>
#include <cstdint>
#include <cstring>

#define Bsz 256
#define Tt  200
#define Dd  128
#define Oo  128
#define RPB 2
#define NBLK (Bsz/RPB)     // 128 scan CTAs
#define NTHR 256
#define SCTH 512           // scan threads: 4 k-groups x 128 h-threads
#define SGRP 4
#define RESG 16            // resident bf16 k-slices per group (64 total)
#define RES_K (SGRP*RESG)
#define KPAD 272           // 256 k's + 16 zero pad for prefetch overrun
#define BT  (Bsz*Tt)       // 51200
#define RPP 16             // bt-rows per G-precompute CTA
#define EROWS 32           // bt-rows per epilogue CTA

typedef unsigned long long u64;

// ---------------- device globals (no allocs allowed) ----------------
__device__ __align__(16) float4 g_A4 [KPAD * 256];   // fp32 A: [k][h]=(Ai,Af,Ao,Ac)[h][k], k in [z|zp]
// bf16 gate weights: [k][hid] uint4 = { if(h0), oc(h0), if(h1), oc(h1) }; h0=hid, h1=hid+128
__device__ __align__(16) unsigned int g_Bhh[KPAD * 128 * 4];
__device__ __align__(16) float4 g_bias4[256];        // folded gate biases
__device__ float  g_WmT[4 * 64 * 256];               // transposed W*[:,0:64]: [g][m][h]
__device__ float  g_Wqh[64 * 256];                   // Wq_h = Wq[:,256:384] @ Wfc   [m][hc]
__device__ float  g_bqe[64];                         // bq + Wq[:,256:] @ bfc
__device__ __align__(8) float2 g_WfcT2[128 * 128];   // [hp][o] = (Wfc[o][2hp], Wfc[o][2hp+1])
__device__ float  g_wzd[128], g_wzpd[128];
__device__ __align__(16) float4 g_G4[(long)BT * 256];// 200 MB: precomputed A@[z,zp]+bias
__device__ float  g_H [(long)BT * 256];              // 50 MB: h_t for the epilogue

// ---------------- helpers ----------------
__device__ __forceinline__ float fast_sigmoid(float x) { return 1.0f / (1.0f + __expf(-x)); }
__device__ __forceinline__ float fast_tanh(float x)    { return 1.0f - 2.0f / (__expf(2.0f * x) + 1.0f); }
__device__ __forceinline__ u64 pack2(float lo, float hi) {
    u64 r; asm("mov.b64 %0, {%1, %2};" : "=l"(r) : "f"(lo), "f"(hi)); return r;
}
__device__ __forceinline__ u64 dup2(float v) {
    u64 r; asm("mov.b64 %0, {%1, %1};" : "=l"(r) : "f"(v)); return r;
}
__device__ __forceinline__ void unpack2(u64 v, float& lo, float& hi) {
    asm("mov.b64 {%0, %1}, %2;" : "=f"(lo), "=f"(hi) : "l"(v));
}
__device__ __forceinline__ void fma2(u64& d, u64 a, u64 b) {
    asm("fma.rn.f32x2 %0, %1, %2, %0;" : "+l"(d) : "l"(a), "l"(b));
}
__device__ __forceinline__ u64 add2(u64 a, u64 b) {
    u64 r; asm("add.rn.f32x2 %0, %1, %2;" : "=l"(r) : "l"(a), "l"(b)); return r;
}
__device__ __forceinline__ ulonglong2 ldcg_v2(const ulonglong2* p) {
    ulonglong2 v;
    asm("ld.global.cg.v2.b64 {%0, %1}, [%2];" : "=l"(v.x), "=l"(v.y) : "l"(p));
    return v;
}
// bf16x2 (packed in 32-bit) -> f32x2 in a 64-bit lane: fp32 = bf16 << 16 (exact)
__device__ __forceinline__ u64 bf2f2(unsigned int w) {
    unsigned int lo = w << 16;
    unsigned int hi = w & 0xffff0000u;
    u64 r; asm("mov.b64 %0, {%1, %2};" : "=l"(r) : "r"(lo), "r"(hi)); return r;
}
__device__ __forceinline__ unsigned short f2bf(float x) {
    __nv_bfloat16 b = __float2bfloat16(x);
    unsigned short s; memcpy(&s, &b, 2); return s;
}

// ================= prep0: transpose W*[:,0:64] for coalesced prep2 =================
__global__ void prep0_kernel(const float* __restrict__ Wi, const float* __restrict__ Wf,
                             const float* __restrict__ Wo, const float* __restrict__ Wc)
{
    int m = blockIdx.x, h = threadIdx.x;      // grid 64, block 256
    g_WmT[(0 * 64 + m) * 256 + h] = Wi[h * 320 + m];
    g_WmT[(1 * 64 + m) * 256 + h] = Wf[h * 320 + m];
    g_WmT[(2 * 64 + m) * 256 + h] = Wo[h * 320 + m];
    g_WmT[(3 * 64 + m) * 256 + h] = Wc[h * 320 + m];
}

// ================= prep1: Wq_h = Wq_xi @ Wfc ; bq_eff =================
__global__ void prep1_kernel(const float* __restrict__ Wq, const float* __restrict__ Wfc,
                             const float* __restrict__ bq, const float* __restrict__ bfc)
{
    int m = blockIdx.x, hc = threadIdx.x;     // grid 64, block 256
    float s = 0.0f;
    for (int o = 0; o < 128; o++)
        s = fmaf(Wq[m * 384 + 256 + o], Wfc[o * 256 + hc], s);
    g_Wqh[m * 256 + hc] = s;
    if (hc == 0) {
        float s2 = bq[m];
        for (int o = 0; o < 128; o++)
            s2 = fmaf(Wq[m * 384 + 256 + o], bfc[o], s2);
        g_bqe[m] = s2;
    }
}

// ================= prep2: fold A (fp32), Bh (bf16), biases; misc =================
__global__ void prep2_kernel(const float* __restrict__ Wz, const float* __restrict__ Wzp,
                             const float* __restrict__ Wq,
                             const float* __restrict__ Wi, const float* __restrict__ bi,
                             const float* __restrict__ Wf, const float* __restrict__ bf,
                             const float* __restrict__ Wo, const float* __restrict__ bo,
                             const float* __restrict__ Wc, const float* __restrict__ bc,
                             const float* __restrict__ Wfc)
{
    int k = blockIdx.x, h = threadIdx.x;      // grid KPAD(272), block 256
    float4 bh = make_float4(0.f, 0.f, 0.f, 0.f);
    float4 a  = make_float4(0.f, 0.f, 0.f, 0.f);
    if (k < 256) {
        bh.x = Wi[h * 320 + 64 + k];
        bh.y = Wf[h * 320 + 64 + k];
        bh.z = Wo[h * 320 + 64 + k];
        bh.w = Wc[h * 320 + 64 + k];
        for (int m = 0; m < 64; m++) {
            float q  = Wq[m * 384 + k];          // uniform across CTA
            float qh = g_Wqh[m * 256 + k];       // uniform across CTA
            float wi = g_WmT[(0 * 64 + m) * 256 + h];   // coalesced
            float wf = g_WmT[(1 * 64 + m) * 256 + h];
            float wo = g_WmT[(2 * 64 + m) * 256 + h];
            float wc = g_WmT[(3 * 64 + m) * 256 + h];
            a.x = fmaf(wi, q, a.x);  a.y = fmaf(wf, q, a.y);
            a.z = fmaf(wo, q, a.z);  a.w = fmaf(wc, q, a.w);
            bh.x = fmaf(wi, qh, bh.x); bh.y = fmaf(wf, qh, bh.y);
            bh.z = fmaf(wo, qh, bh.z); bh.w = fmaf(wc, qh, bh.w);
        }
    }
    g_A4[k * 256 + h] = a;                       // fp32 A (zero pad for k>=256)
    // bf16 Bh pack: unit [k][h&127], halves by h>>7
    {
        unsigned int u_if = (unsigned int)f2bf(bh.x) | ((unsigned int)f2bf(bh.y) << 16);
        unsigned int u_oc = (unsigned int)f2bf(bh.z) | ((unsigned int)f2bf(bh.w) << 16);
        unsigned int* dst = g_Bhh + (k * 128 + (h & 127)) * 4 + ((h >> 7) << 1);
        dst[0] = u_if;
        dst[1] = u_oc;
    }
    if (k == 0) {
        float4 b4 = make_float4(bi[h], bf[h], bo[h], bc[h]);
        for (int m = 0; m < 64; m++) {
            float e = g_bqe[m];
            b4.x = fmaf(g_WmT[(0 * 64 + m) * 256 + h], e, b4.x);
            b4.y = fmaf(g_WmT[(1 * 64 + m) * 256 + h], e, b4.y);
            b4.z = fmaf(g_WmT[(2 * 64 + m) * 256 + h], e, b4.z);
            b4.w = fmaf(g_WmT[(3 * 64 + m) * 256 + h], e, b4.w);
        }
        g_bias4[h] = b4;
    }
    if (k == 1 && h < 128) {
        g_wzd[h]  = Wz[h * 128 + h];
        g_wzpd[h] = Wzp[h * 128 + h];
    }
    if (k < 128 && h < 128)
        g_WfcT2[k * 128 + h] = make_float2(Wfc[h * 256 + 2 * k], Wfc[h * 256 + 2 * k + 1]);
}

// ================= G precompute: G = A(fp32) @ [z,zp] + bias; u undup, dup in-register ==
__global__ __launch_bounds__(NTHR, 2) void gpre_kernel(
    const float* __restrict__ inp, const float* __restrict__ xmean,
    const float* __restrict__ bz,  const float* __restrict__ bzp)
{
    __shared__ __align__(16) float su[RPP * 256];    // 16 KB, NOT duplicated
    __shared__ float s_wzd[128], s_bz[128], s_wzpd[128], s_bzp[128];

    const int tid = threadIdx.x;
    const int bt0 = blockIdx.x * RPP;                 // grid = BT/RPP = 3200

    if (tid < 128) {
        s_wzd[tid] = g_wzd[tid];   s_bz[tid]  = bz[tid];
        s_wzpd[tid] = g_wzpd[tid]; s_bzp[tid] = bzp[tid];
    }
    __syncthreads();

    const long cs = (long)Tt * Dd;
    for (int e = tid; e < RPP * 128; e += NTHR) {
        int row = e >> 7, j = e & 127;
        int bt = bt0 + row, b = bt / Tt, t = bt - b * Tt;
        long base = ((long)b * 6 * Tt + t) * (long)Dd + j;
        float x   = inp[base];
        float xl  = inp[base + 1 * cs];
        float mk  = inp[base + 2 * cs];
        float dl  = inp[base + 3 * cs];
        float xlb = inp[base + 4 * cs];
        float dlb = inp[base + 5 * cs];
        float xm  = xmean[((long)b * Tt + t) * (long)Dd + j];
        float dz  = __expf(-fmaxf(fmaf(dl,  s_wzd[j],  s_bz[j]),  0.0f));
        float dzp = __expf(-fmaxf(fmaf(dlb, s_wzpd[j], s_bzp[j]), 0.0f));
        su[row * 256 + j]       = mk * x + (1.0f - mk) * (dz  * xl  + (1.0f - dz)  * xm);
        su[row * 256 + 128 + j] = mk * x + (1.0f - mk) * (dzp * xlb + (1.0f - dzp) * xm);
    }
    __syncthreads();

    u64 aif[RPP], aoc[RPP];
    {
        float4 b4 = g_bias4[tid];
#pragma unroll
        for (int r = 0; r < RPP; r++) { aif[r] = pack2(b4.x, b4.y); aoc[r] = pack2(b4.z, b4.w); }
    }
    const ulonglong2* __restrict__ wg = reinterpret_cast<const ulonglong2*>(g_A4) + tid;
    const float4* su4 = reinterpret_cast<const float4*>(su);
    ulonglong2 wb[4];
#pragma unroll
    for (int i = 0; i < 4; i++) wb[i] = ldcg_v2(wg + i * 256);
#pragma unroll 1
    for (int k0 = 0; k0 < 256; k0 += 4) {
        ulonglong2 w0 = wb[0], w1 = wb[1], w2v = wb[2], w3 = wb[3];
        wb[0] = ldcg_v2(wg + (k0 + 4) * 256);   // KPAD zero-pad covers overrun
        wb[1] = ldcg_v2(wg + (k0 + 5) * 256);
        wb[2] = ldcg_v2(wg + (k0 + 6) * 256);
        wb[3] = ldcg_v2(wg + (k0 + 7) * 256);
        const int kq = k0 >> 2;
#pragma unroll
        for (int r = 0; r < RPP; r++) {
            float4 uu = su4[r * 64 + kq];        // one broadcast LDS.128 per 4 k per row
            u64 d0 = dup2(uu.x), d1 = dup2(uu.y), d2 = dup2(uu.z), d3 = dup2(uu.w);
            fma2(aif[r], w0.x,  d0); fma2(aoc[r], w0.y,  d0);
            fma2(aif[r], w1.x,  d1); fma2(aoc[r], w1.y,  d1);
            fma2(aif[r], w2v.x, d2); fma2(aoc[r], w2v.y, d2);
            fma2(aif[r], w3.x,  d3); fma2(aoc[r], w3.y,  d3);
        }
    }
#pragma unroll
    for (int r = 0; r < RPP; r++) {
        float gi, gf, go, gc;
        unpack2(aif[r], gi, gf); unpack2(aoc[r], go, gc);
        g_G4[(long)(bt0 + r) * 256 + tid] = make_float4(gi, gf, go, gc);
    }
}

// ================= scan: 128 CTAs (2 rows), 512 thr, 64 resident bf16 k + 192 streamed ==
__global__ __launch_bounds__(SCTH, 1) void scan_kernel()
{
    extern __shared__ __align__(16) char smraw[];
    uint4* resW16 = reinterpret_cast<uint4*>(smraw);              // [RES_K][128]   131072 B
    u64* hdup = reinterpret_cast<u64*>(smraw + RES_K * 128 * 16); // [2][RPB][256]    8192 B
    u64* part = reinterpret_cast<u64*>(smraw + RES_K * 128 * 16 + 8192); // [4][RPB][256][2] 32768 B

    const int tid = threadIdx.x;
    const int g   = tid >> 7;          // k-group 0..3
    const int hid = tid & 127;
    const int h0  = hid, h1 = hid + 128;
    const int b0  = blockIdx.x * RPB;
    const int kb  = g << 6;            // group k-base: 0,64,128,192

    // resident bf16 slices: slice s -> global k = 64*(s>>4) + (s&15)
    {
        const uint4* src = reinterpret_cast<const uint4*>(g_Bhh);
        for (int i = tid; i < RES_K * 128; i += SCTH) {
            int s = i >> 7, hh = i & 127;
            int kg = ((s >> 4) << 6) + (s & 15);
            resW16[i] = src[kg * 128 + hh];
        }
    }
    for (int i = tid; i < 2 * RPB * 256; i += SCTH) hdup[i] = 0ull;        // h0 = 0

    float c_reg = 0.0f;                // reduce thread owns 1 output (row tid>>8, h tid&255)
    __syncthreads();

    const uint4* __restrict__ wb16 = reinterpret_cast<const uint4*>(g_Bhh) + hid;  // [k][hid]
    const uint4* __restrict__ rws  = resW16 + (g * RESG) * 128 + hid;
    const float4* __restrict__ G4 = g_G4;

    for (int t = 0; t < Tt; t++) {
        const int cur = t & 1, prv = cur ^ 1;
        const u64* hp = hdup + prv * (RPB * 256);

        // groups 1,2 issue G loads now; consumed at deposit (GEMM hides latency)
        float4 gvl[RPB];
        if (g == 1) {
#pragma unroll
            for (int r = 0; r < RPB; r++) gvl[r] = G4[((long)(b0 + r) * Tt + t) * 256 + h0];
        } else if (g == 2) {
#pragma unroll
            for (int r = 0; r < RPB; r++) gvl[r] = G4[((long)(b0 + r) * Tt + t) * 256 + h1];
        }

        u64 aif0[RPB], aoc0[RPB], aif1[RPB], aoc1[RPB];
#pragma unroll
        for (int r = 0; r < RPB; r++) { aif0[r] = 0ull; aoc0[r] = 0ull; aif1[r] = 0ull; aoc1[r] = 0ull; }

        // prefetch first 4 streamed k's (k = kb+RESG .. kb+RESG+3)
        uint4 wq[4];
#pragma unroll
        for (int i = 0; i < 4; i++) wq[i] = __ldcg(wb16 + (kb + RESG + i) * 128);

        // ---- resident part: 16 k (bf16 SMEM), global k = kb + j ----
#pragma unroll 4
        for (int j = 0; j < RESG; j += 2) {
            uint4 a0 = rws[j * 128], a1 = rws[(j + 1) * 128];
            u64 wa_if0 = bf2f2(a0.x), wa_oc0 = bf2f2(a0.y), wa_if1 = bf2f2(a0.z), wa_oc1 = bf2f2(a0.w);
            u64 wc_if0 = bf2f2(a1.x), wc_oc0 = bf2f2(a1.y), wc_if1 = bf2f2(a1.z), wc_oc1 = bf2f2(a1.w);
#pragma unroll
            for (int r = 0; r < RPB; r++) {
                ulonglong2 hh = *reinterpret_cast<const ulonglong2*>(&hp[r * 256 + kb + j]);
                fma2(aif0[r], wa_if0, hh.x); fma2(aoc0[r], wa_oc0, hh.x);
                fma2(aif1[r], wa_if1, hh.x); fma2(aoc1[r], wa_oc1, hh.x);
                fma2(aif0[r], wc_if0, hh.y); fma2(aoc0[r], wc_oc0, hh.y);
                fma2(aif1[r], wc_if1, hh.y); fma2(aoc1[r], wc_oc1, hh.y);
            }
        }

        // ---- streamed part: 48 k (bf16), 12 iterations of 4 k ----
#pragma unroll 1
        for (int k0 = kb + RESG; k0 < kb + 64; k0 += 4) {
            uint4 a0 = wq[0], a1 = wq[1], a2 = wq[2], a3 = wq[3];
            wq[0] = __ldcg(wb16 + (k0 + 4) * 128);   // KPAD pad covers overrun
            wq[1] = __ldcg(wb16 + (k0 + 5) * 128);
            wq[2] = __ldcg(wb16 + (k0 + 6) * 128);
            wq[3] = __ldcg(wb16 + (k0 + 7) * 128);
            {
                u64 wa_if0 = bf2f2(a0.x), wa_oc0 = bf2f2(a0.y), wa_if1 = bf2f2(a0.z), wa_oc1 = bf2f2(a0.w);
                u64 wc_if0 = bf2f2(a1.x), wc_oc0 = bf2f2(a1.y), wc_if1 = bf2f2(a1.z), wc_oc1 = bf2f2(a1.w);
#pragma unroll
                for (int r = 0; r < RPB; r++) {
                    ulonglong2 hh = *reinterpret_cast<const ulonglong2*>(&hp[r * 256 + k0]);
                    fma2(aif0[r], wa_if0, hh.x); fma2(aoc0[r], wa_oc0, hh.x);
                    fma2(aif1[r], wa_if1, hh.x); fma2(aoc1[r], wa_oc1, hh.x);
                    fma2(aif0[r], wc_if0, hh.y); fma2(aoc0[r], wc_oc0, hh.y);
                    fma2(aif1[r], wc_if1, hh.y); fma2(aoc1[r], wc_oc1, hh.y);
                }
            }
            {
                u64 wa_if0 = bf2f2(a2.x), wa_oc0 = bf2f2(a2.y), wa_if1 = bf2f2(a2.z), wa_oc1 = bf2f2(a2.w);
                u64 wc_if0 = bf2f2(a3.x), wc_oc0 = bf2f2(a3.y), wc_if1 = bf2f2(a3.z), wc_oc1 = bf2f2(a3.w);
#pragma unroll
                for (int r = 0; r < RPB; r++) {
                    ulonglong2 hh = *reinterpret_cast<const ulonglong2*>(&hp[r * 256 + k0 + 2]);
                    fma2(aif0[r], wa_if0, hh.x); fma2(aoc0[r], wa_oc0, hh.x);
                    fma2(aif1[r], wa_if1, hh.x); fma2(aoc1[r], wa_oc1, hh.x);
                    fma2(aif0[r], wc_if0, hh.y); fma2(aoc0[r], wc_oc0, hh.y);
                    fma2(aif1[r], wc_if1, hh.y); fma2(aoc1[r], wc_oc1, hh.y);
                }
            }
        }

        // ---- fold G, deposit partials ----
        if (g == 1) {
#pragma unroll
            for (int r = 0; r < RPB; r++) {
                aif0[r] = add2(aif0[r], pack2(gvl[r].x, gvl[r].y));
                aoc0[r] = add2(aoc0[r], pack2(gvl[r].z, gvl[r].w));
            }
        } else if (g == 2) {
#pragma unroll
            for (int r = 0; r < RPB; r++) {
                aif1[r] = add2(aif1[r], pack2(gvl[r].x, gvl[r].y));
                aoc1[r] = add2(aoc1[r], pack2(gvl[r].z, gvl[r].w));
            }
        }
#pragma unroll
        for (int r = 0; r < RPB; r++) {
            ulonglong2 p0; p0.x = aif0[r]; p0.y = aoc0[r];
            ulonglong2 p1; p1.x = aif1[r]; p1.y = aoc1[r];
            *reinterpret_cast<ulonglong2*>(&part[((g * RPB + r) * 256 + h0) * 2]) = p0;
            *reinterpret_cast<ulonglong2*>(&part[((g * RPB + r) * 256 + h1) * 2]) = p1;
        }
        __syncthreads();

        // ---- all threads: 4-way reduce, activations, publish (1 output/thread) ----
        {
            const int hh_ = tid & 255;
            const int rr  = tid >> 8;           // 0 or 1
            ulonglong2 p0 = *reinterpret_cast<const ulonglong2*>(&part[((0 * RPB + rr) * 256 + hh_) * 2]);
            ulonglong2 p1 = *reinterpret_cast<const ulonglong2*>(&part[((1 * RPB + rr) * 256 + hh_) * 2]);
            ulonglong2 p2 = *reinterpret_cast<const ulonglong2*>(&part[((2 * RPB + rr) * 256 + hh_) * 2]);
            ulonglong2 p3 = *reinterpret_cast<const ulonglong2*>(&part[((3 * RPB + rr) * 256 + hh_) * 2]);
            u64 tif = add2(add2(p0.x, p1.x), add2(p2.x, p3.x));
            u64 toc = add2(add2(p0.y, p1.y), add2(p2.y, p3.y));
            float ai, afv, ao, ac;
            unpack2(tif, ai, afv); unpack2(toc, ao, ac);
            float ig = fast_sigmoid(ai), fg = fast_sigmoid(afv);
            float og = fast_sigmoid(ao), ct = fast_tanh(ac);
            c_reg = fg * c_reg + ig * ct;
            float hv = og * fast_tanh(c_reg);
            hdup[cur * (RPB * 256) + rr * 256 + hh_] = dup2(hv);
            g_H[((long)(b0 + rr) * Tt + t) * 256 + hh_] = hv;
        }
        __syncthreads();
    }
}

// ================= epilogue: out = H @ Wfc^T + bfc (fully parallel) =================
__global__ __launch_bounds__(NTHR) void epi_kernel(const float* __restrict__ bfc,
                                                   float* __restrict__ out)
{
    __shared__ __align__(16) float hs[EROWS * 256];   // 32 KB
    const int tid = threadIdx.x;
    const int bt0 = blockIdx.x * EROWS;               // grid = BT/EROWS = 1600

    for (int e = tid; e < EROWS * 256; e += NTHR)
        hs[e] = g_H[(long)bt0 * 256 + e];
    __syncthreads();

    const int o  = tid & 127;
    const int rb = (tid >> 7) * 16;                   // rows rb .. rb+15
    u64 acc[16];
#pragma unroll
    for (int r = 0; r < 16; r++) acc[r] = 0ull;

    const u64* __restrict__ w2 = reinterpret_cast<const u64*>(g_WfcT2) + o;
#pragma unroll 4
    for (int hpi = 0; hpi < 128; hpi++) {
        u64 w = w2[hpi * 128];
#pragma unroll
        for (int r = 0; r < 16; r++)
            fma2(acc[r], w, *reinterpret_cast<const u64*>(&hs[(rb + r) * 256 + 2 * hpi]));
    }
    const float bo_ = bfc[o];
#pragma unroll
    for (int r = 0; r < 16; r++) {
        float x0, x1; unpack2(acc[r], x0, x1);
        out[(long)(bt0 + rb + r) * Oo + o] = bo_ + x0 + x1;
    }
}

// ================= launch =================
#define SCAN_SMEM (RES_K*128*16 + 2*RPB*256*8 + SGRP*RPB*256*2*8)   // 131072+8192+32768 = 172032

extern "C" void kernel_launch(void* const* d_in, const int* in_sizes, int n_in,
                              void* d_out, int out_size)
{
    const float* inp   = (const float*)d_in[0];
    const float* xmean = (const float*)d_in[1];
    const float* Wz    = (const float*)d_in[2];
    const float* bz    = (const float*)d_in[3];
    const float* Wzp   = (const float*)d_in[4];
    const float* bzp   = (const float*)d_in[5];
    const float* Wq    = (const float*)d_in[6];
    const float* bq    = (const float*)d_in[7];
    const float* Wi    = (const float*)d_in[8];
    const float* bi    = (const float*)d_in[9];
    const float* Wf    = (const float*)d_in[10];
    const float* bf    = (const float*)d_in[11];
    const float* Wo    = (const float*)d_in[12];
    const float* bo    = (const float*)d_in[13];
    const float* Wc    = (const float*)d_in[14];
    const float* bc    = (const float*)d_in[15];
    const float* Wfc   = (const float*)d_in[16];
    const float* bfc   = (const float*)d_in[17];
    float* out = (float*)d_out;

    cudaFuncSetAttribute(scan_kernel, cudaFuncAttributeMaxDynamicSharedMemorySize, SCAN_SMEM);

    prep0_kernel<<<64, 256>>>(Wi, Wf, Wo, Wc);
    prep1_kernel<<<64, 256>>>(Wq, Wfc, bq, bfc);
    prep2_kernel<<<KPAD, 256>>>(Wz, Wzp, Wq, Wi, bi, Wf, bf, Wo, bo, Wc, bc, Wfc);
    gpre_kernel<<<BT / RPP, NTHR>>>(inp, xmean, bz, bzp);
    scan_kernel<<<NBLK, SCTH, SCAN_SMEM>>>();
    epi_kernel<<<BT / EROWS, NTHR>>>(bfc, out);
}